// round 9
// baseline (speedup 1.0000x reference)
#include <cuda_runtime.h>
#include <cuda_bf16.h>

// Problem constants
#define BSZ   1024
#define TLEN  512
#define NX    32
#define NU    8
#define HN    64
#define G4    256        // 4*H
#define HB    8          // batch rows per recurrent CTA
#define NCTA  (BSZ / HB) // 128 recurrent CTAs
#define RTHR  256        // 8 warps = 2/SMSP

// 512 MB scratch for hoisted layer-0 input projection.
// Layout: [t][b][u*4+g] where g in {i,f,g,o} of unit u  (gate-interleaved!)
__device__ float g_xproj[(size_t)TLEN * BSZ * G4];

typedef unsigned long long ull;

// ---------------------------------------------------------------------------
// packed f32x2 helpers (Blackwell FFMA2 via PTX)
// ---------------------------------------------------------------------------
__device__ __forceinline__ ull pack2(float lo, float hi) {
    ull r; asm("mov.b64 %0, {%1, %2};" : "=l"(r) : "f"(lo), "f"(hi)); return r;
}
__device__ __forceinline__ ull pack_dup(float v) {
    ull r; asm("mov.b64 %0, {%1, %1};" : "=l"(r) : "f"(v)); return r;
}
__device__ __forceinline__ void fma2(ull& d, ull a, ull b) {
    asm("fma.rn.f32x2 %0, %1, %2, %0;" : "+l"(d) : "l"(a), "l"(b));
}
__device__ __forceinline__ float2 unpack2(ull v) {
    float2 f; asm("mov.b64 {%0, %1}, %2;" : "=f"(f.x), "=f"(f.y) : "l"(v)); return f;
}

__device__ __forceinline__ float sig_f(float x) {
    return __fdividef(1.0f, 1.0f + __expf(-x));
}
__device__ __forceinline__ float tanh_f(float x) {
    return 1.0f - __fdividef(2.0f, __expf(2.0f * x) + 1.0f);
}

// ---------------------------------------------------------------------------
// Kernel 1: layer-0 input projection GEMM (gate-interleaved output layout)
// Thread tid computes gate j = (tid>>2) + (tid&3)*64 and writes at inner
// offset tid, so [b][u*4+g] holds {i,f,g,o} of unit u adjacent -> the recur
// kernel loads per-batch xp as ONE LDG.128 whose halves are (i,f),(g,o).
// ---------------------------------------------------------------------------
__global__ void __launch_bounds__(256) xproj_kernel(
    const float* __restrict__ x, const float* __restrict__ u,
    const float* __restrict__ Wih0, const float* __restrict__ bih0,
    const float* __restrict__ bhh0)
{
    const int cta = blockIdx.x;
    const int t  = cta >> 4;
    const int b0 = (cta & 15) << 6;

    __shared__ float sseq[64][40];
    const int tid = threadIdx.x;

    for (int idx = tid; idx < 64 * 32; idx += 256) {
        int r = idx >> 5, i = idx & 31;
        sseq[r][i] = x[(size_t)(b0 + r) * (TLEN * NX) + t * NX + i];
    }
    for (int idx = tid; idx < 64 * 8; idx += 256) {
        int r = idx >> 3, i = idx & 7;
        sseq[r][32 + i] = u[(size_t)(b0 + r) * (TLEN * NU) + t * NU + i];
    }

    const int j = (tid >> 2) + (tid & 3) * 64;   // gate row this thread computes
    const ull* wrow = (const ull*)(Wih0 + (size_t)j * 40);
    ull wd[20];
#pragma unroll
    for (int q = 0; q < 20; q++) wd[q] = wrow[q];
    const float bias = __ldg(&bih0[j]) + __ldg(&bhh0[j]);

    __syncthreads();

    // write at inner offset tid (coalesced; == u*4+g for u=tid>>2, g=tid&3)
    float* outp = &g_xproj[(size_t)t * (BSZ * G4) + (size_t)b0 * G4 + tid];
#pragma unroll 2
    for (int r = 0; r < 64; r++) {
        const ulonglong2* s2 = (const ulonglong2*)sseq[r];
        ull acc = pack2(bias, 0.0f);
#pragma unroll
        for (int q = 0; q < 10; q++) {
            ulonglong2 v = s2[q];
            fma2(acc, v.x, wd[2 * q + 0]);
            fma2(acc, v.y, wd[2 * q + 1]);
        }
        float2 f = unpack2(acc);
        outp[(size_t)r * G4] = f.x + f.y;
    }
}

// ---------------------------------------------------------------------------
// Kernel 2: persistent 2-layer LSTM recurrence + final FC
// grid = 128 CTAs x 256 threads. CTA owns batches [8r, 8r+8).
// Thread (u = tid>>2, q = tid&3): unit u, batches {2q, 2q+1}, ALL 4 gates.
//   - weight panels: wq[k][u] = float4(Wi,Wf,Wg,Wo)[u][k]
//     -> per k one LDS.128; .xy = (i,f) pair, .zw = (g,o) pair (no weight dup)
//   - h buffers: float4 slot (k2,q) = {h[2k2][2q],h[2k2][2q+1],
//                                      h[2k2+1][2q],h[2k2+1][2q+1]}
//     -> per 2 k one LDS.128; values dup'd into f32x2 via pack_dup
//   - double-buffered h1,h2: exactly ONE __syncthreads per timestep
// Schedule:  mv0(read h1[p^1],xp) -> c1/h1 -> write h1[p] -> BAR ->
//            mv1(read h1[p], h2[p^1]) -> c2/h2 -> write h2[p]      (p = t&1)
// ---------------------------------------------------------------------------
extern __shared__ float smem_dyn[];

__global__ void __launch_bounds__(RTHR, 1) lstm_recur_kernel(
    const float* __restrict__ Whh0,
    const float* __restrict__ Wih1, const float* __restrict__ Whh1,
    const float* __restrict__ bih1, const float* __restrict__ bhh1,
    const float* __restrict__ Wfc,  const float* __restrict__ bfc,
    float* __restrict__ out)
{
    // dynamic smem (floats):
    float* wq0 = smem_dyn;            // 64k x 64u x 4g = 16384  (Whh0)
    float* wq1 = wq0 + 16384;         // 128k x 64u x 4g = 32768 (Wih1|Whh1)
    float* h1b = wq1 + 32768;         // 2 buffers x 512
    float* h2b = h1b + 1024;          // 2 buffers x 512
    float* b1q = h2b + 1024;          // 64u x 4g = 256
    // total 51456 floats = 205824 B

    const int tid = threadIdx.x;
    const int u   = tid >> 2;         // unit 0..63
    const int q   = tid & 3;          // batch quarter: batches {2q, 2q+1}
    const int b0  = blockIdx.x * HB;
    const int hoff = (u >> 1) * 16 + q * 4 + (u & 1) * 2;  // h write offset

    // ---- stage weights: wq[(k*64+u)*4+g] = W[u + g*64][k] ----
    for (int idx = tid; idx < 16384; idx += RTHR) {
        int k = idx >> 8, m = (idx >> 2) & 63, g = idx & 3;
        wq0[idx] = Whh0[(m + g * 64) * 64 + k];
    }
    for (int idx = tid; idx < 32768; idx += RTHR) {
        int k = idx >> 8, m = (idx >> 2) & 63, g = idx & 3;
        wq1[idx] = (k < 64) ? Wih1[(m + g * 64) * 64 + k]
                            : Whh1[(m + g * 64) * 64 + (k - 64)];
    }
    {
        int m = tid >> 2, g = tid & 3;
        b1q[tid] = bih1[m + g * 64] + bhh1[m + g * 64];
    }
    for (int idx = tid; idx < 2048; idx += RTHR) h1b[idx] = 0.0f;  // zeros h1b+h2b
    __syncthreads();

    // per-thread bias pair (loop-invariant)
    ulonglong2 bq = *(const ulonglong2*)(b1q + u * 4);

    float2 c1 = {0.f, 0.f}, c2 = {0.f, 0.f};

    // xp for t=0: one LDG.128 per batch; halves are (i,f) and (g,o) pairs
    ulonglong2 xc0, xc1;
    {
        const float* xp = &g_xproj[(size_t)(b0 + 2 * q) * G4 + u * 4];
        xc0 = *(const ulonglong2*)xp;
        xc1 = *(const ulonglong2*)(xp + G4);
    }

#pragma unroll 1
    for (int t = 0; t < TLEN; t++) {
        const int p = t & 1;
        const float* h1r = h1b + (p ^ 1) * 512;
        float*       h1w = h1b + p * 512;
        const float* h2r = h2b + (p ^ 1) * 512;
        float*       h2w = h2b + p * 512;

        // ---- mv0: gates0 = xp(t) + h1(t-1) @ Whh0^T ----
        ull aif0 = xc0.x, ago0 = xc0.y;   // batch 2q
        ull aif1 = xc1.x, ago1 = xc1.y;   // batch 2q+1
#pragma unroll 8
        for (int k2 = 0; k2 < 32; k2++) {
            ulonglong2 w0 = *(const ulonglong2*)(wq0 + (k2 * 128 + u) * 4);
            ulonglong2 w1 = *(const ulonglong2*)(wq0 + (k2 * 128 + 64 + u) * 4);
            float4 hv = *(const float4*)(h1r + (k2 * 4 + q) * 4);
            ull d0 = pack_dup(hv.x), d1 = pack_dup(hv.y);
            ull d2 = pack_dup(hv.z), d3 = pack_dup(hv.w);
            fma2(aif0, d0, w0.x); fma2(ago0, d0, w0.y);
            fma2(aif1, d1, w0.x); fma2(ago1, d1, w0.y);
            fma2(aif0, d2, w1.x); fma2(ago0, d2, w1.y);
            fma2(aif1, d3, w1.x); fma2(ago1, d3, w1.y);
        }

        // prefetch xp(t+1) (consumed next iteration; DRAM latency hidden)
        ulonglong2 xn0, xn1;
        {
            int tn = t + 1; if (tn == TLEN) tn = 0;
            const float* xp = &g_xproj[(size_t)tn * (BSZ * G4)
                                       + (size_t)(b0 + 2 * q) * G4 + u * 4];
            xn0 = *(const ulonglong2*)xp;
            xn1 = *(const ulonglong2*)(xp + G4);
        }

        // ---- c1/h1 update (inline, no gate exchange) ----
        {
            float2 pif = unpack2(aif0), pgo = unpack2(ago0);
            float i_ = sig_f(pif.x), f_ = sig_f(pif.y);
            float g_ = tanh_f(pgo.x), o_ = sig_f(pgo.y);
            c1.x = f_ * c1.x + i_ * g_;
            float ha = o_ * tanh_f(c1.x);
            pif = unpack2(aif1); pgo = unpack2(ago1);
            i_ = sig_f(pif.x); f_ = sig_f(pif.y);
            g_ = tanh_f(pgo.x); o_ = sig_f(pgo.y);
            c1.y = f_ * c1.y + i_ * g_;
            float hb = o_ * tanh_f(c1.y);
            *(float2*)(h1w + hoff) = make_float2(ha, hb);
        }
        __syncthreads();   // the ONLY barrier per step

        // ---- mv1: gates1 = b1 + h1(t)@Wih1^T + h2(t-1)@Whh1^T ----
        aif0 = bq.x; ago0 = bq.y;
        aif1 = bq.x; ago1 = bq.y;
#pragma unroll 8
        for (int k2 = 0; k2 < 32; k2++) {          // k in [0,64): Wih1 with h1(t)
            ulonglong2 w0 = *(const ulonglong2*)(wq1 + (k2 * 128 + u) * 4);
            ulonglong2 w1 = *(const ulonglong2*)(wq1 + (k2 * 128 + 64 + u) * 4);
            float4 hv = *(const float4*)(h1w + (k2 * 4 + q) * 4);
            ull d0 = pack_dup(hv.x), d1 = pack_dup(hv.y);
            ull d2 = pack_dup(hv.z), d3 = pack_dup(hv.w);
            fma2(aif0, d0, w0.x); fma2(ago0, d0, w0.y);
            fma2(aif1, d1, w0.x); fma2(ago1, d1, w0.y);
            fma2(aif0, d2, w1.x); fma2(ago0, d2, w1.y);
            fma2(aif1, d3, w1.x); fma2(ago1, d3, w1.y);
        }
#pragma unroll 8
        for (int k2 = 0; k2 < 32; k2++) {          // k in [64,128): Whh1 with h2(t-1)
            ulonglong2 w0 = *(const ulonglong2*)(wq1 + 16384 + (k2 * 128 + u) * 4);
            ulonglong2 w1 = *(const ulonglong2*)(wq1 + 16384 + (k2 * 128 + 64 + u) * 4);
            float4 hv = *(const float4*)(h2r + (k2 * 4 + q) * 4);
            ull d0 = pack_dup(hv.x), d1 = pack_dup(hv.y);
            ull d2 = pack_dup(hv.z), d3 = pack_dup(hv.w);
            fma2(aif0, d0, w0.x); fma2(ago0, d0, w0.y);
            fma2(aif1, d1, w0.x); fma2(ago1, d1, w0.y);
            fma2(aif0, d2, w1.x); fma2(ago0, d2, w1.y);
            fma2(aif1, d3, w1.x); fma2(ago1, d3, w1.y);
        }

        // ---- c2/h2 update ----
        {
            float2 pif = unpack2(aif0), pgo = unpack2(ago0);
            float i_ = sig_f(pif.x), f_ = sig_f(pif.y);
            float g_ = tanh_f(pgo.x), o_ = sig_f(pgo.y);
            c2.x = f_ * c2.x + i_ * g_;
            float ha = o_ * tanh_f(c2.x);
            pif = unpack2(aif1); pgo = unpack2(ago1);
            i_ = sig_f(pif.x); f_ = sig_f(pif.y);
            g_ = tanh_f(pgo.x); o_ = sig_f(pgo.y);
            c2.y = f_ * c2.y + i_ * g_;
            float hb = o_ * tanh_f(c2.y);
            *(float2*)(h2w + hoff) = make_float2(ha, hb);
        }
        // no barrier here: next mv0 doesn't touch h2; mv1(t+1)'s h2 read is
        // ordered by the barrier inside iteration t+1.

        xc0 = xn0; xc1 = xn1;
    }

    __syncthreads();
    // ---- final FC: out[b][n] = b_fc[n] + sum_k h2[b][k] * W_fc[n][k] ----
    {
        const float* h2f = h2b + ((TLEN - 1) & 1) * 512;
        const int b = tid >> 5, n = tid & 31;
        float acc = __ldg(&bfc[n]);
#pragma unroll
        for (int k = 0; k < HN; k++) {
            float hv = h2f[(k >> 1) * 16 + (b >> 1) * 4 + (k & 1) * 2 + (b & 1)];
            acc = fmaf(hv, __ldg(&Wfc[n * HN + k]), acc);
        }
        out[(b0 + b) * NX + n] = acc;
    }
}

// ---------------------------------------------------------------------------
extern "C" void kernel_launch(void* const* d_in, const int* in_sizes, int n_in,
                              void* d_out, int out_size)
{
    const float* x_seq = (const float*)d_in[0];
    const float* u_seq = (const float*)d_in[1];
    const float* Wih0  = (const float*)d_in[2];
    const float* Whh0  = (const float*)d_in[3];
    const float* bih0  = (const float*)d_in[4];
    const float* bhh0  = (const float*)d_in[5];
    const float* Wih1  = (const float*)d_in[6];
    const float* Whh1  = (const float*)d_in[7];
    const float* bih1  = (const float*)d_in[8];
    const float* bhh1  = (const float*)d_in[9];
    const float* Wfc   = (const float*)d_in[10];
    const float* bfc   = (const float*)d_in[11];
    float* out = (float*)d_out;

    const int SMEM_BYTES = 51456 * 4;  // 205824
    cudaFuncSetAttribute(lstm_recur_kernel,
                         cudaFuncAttributeMaxDynamicSharedMemorySize, SMEM_BYTES);

    xproj_kernel<<<TLEN * (BSZ / 64), 256>>>(x_seq, u_seq, Wih0, bih0, bhh0);
    lstm_recur_kernel<<<NCTA, RTHR, SMEM_BYTES>>>(Whh0, Wih1, Whh1, bih1, bhh1,
                                                  Wfc, bfc, out);
}